// round 6
// baseline (speedup 1.0000x reference)
#include <cuda_runtime.h>
#include <math.h>

typedef unsigned long long ull;
typedef unsigned int uint;

#define TT 8192
#define HH 512

// ---------------- scratch ----------------
__device__ float g_h1[(TT + 1) * HH];   // layer-1 hidden seq (slot 0 = h0[0])
__device__ float g_h2[(TT + 1) * HH];   // layer-2 hidden seq (slot 0 = h0[1])
__device__ int   g_c1[64];              // per-producer-block counters, layer 1
__device__ int   g_c2[64];              // per-producer-block counters, layer 2
// counter b == 8*(t+1)  <=>  h{L}[t+1] elements [8b,8b+8) are published

// ---------------- primitives ----------------
__device__ __forceinline__ int ld_acq(const int* p) {
    int v;
    asm volatile("ld.acquire.gpu.global.b32 %0, [%1];" : "=r"(v) : "l"(p) : "memory");
    return v;
}
__device__ __forceinline__ void red_rel(int* p) {
    asm volatile("red.release.gpu.global.add.s32 [%0], %1;" :: "l"(p), "r"(1) : "memory");
}
__device__ __forceinline__ void ffma2(ull& acc, ull w, ull v) {
    asm("fma.rn.f32x2 %0, %1, %2, %0;" : "+l"(acc) : "l"(w), "l"(v));
}
__device__ __forceinline__ float2 unpack2(ull v) {
    float a, b;
    asm("mov.b64 {%0,%1}, %2;" : "=f"(a), "=f"(b) : "l"(v));
    return make_float2(a, b);
}
__device__ __forceinline__ float tanh_fast(float x) {
    float r;
    asm("tanh.approx.f32 %0, %1;" : "=f"(r) : "f"(x));
    return r;
}
__device__ __forceinline__ float sig_fast(float x) {
    return fmaf(tanh_fast(0.5f * x), 0.5f, 0.5f);
}
__device__ __forceinline__ float logsigf_(float z) {
    if (z >= 0.0f) return -log1pf(expf(-z));
    return z - log1pf(expf(z));
}

// ---------------- clear + seed (tiny now: counters + h0 slots only) ----------------
__global__ void clear_kernel(const float* __restrict__ h0) {
    int i = blockIdx.x * blockDim.x + threadIdx.x;
    if (i < 64) { g_c1[i] = 0; g_c2[i] = 0; }
    if (i < HH) {
        g_h1[i] = h0[i];
        g_h2[i] = h0[HH + i];
    }
}

// ---------------- persistent pipelined LSTM ----------------
// 129 blocks x 256 threads.
//   blocks [0,64):   layer 1 (8 outputs each)
//   blocks [64,128): layer 2 (8 outputs each)
//   block 128:       head + BCE loss
// Dot map (as R3): tt = p*8 + s; p in 0..31 (row pair), s in 0..7 (64-col slice);
//   p<16 -> W_ih rows, p>=16 -> W_hh rows.
// Staging: threads [0,128) stage vecA (x[t] or h1[t]); [128,256) stage own h[t-1].
// Each stager acquire-polls the single counter covering its float4, then loads.
__global__ void __launch_bounds__(256, 1) lstm_kernel(
    const float* __restrict__ x,
    const float* __restrict__ truth,
    const float* __restrict__ c0,
    const float* __restrict__ Wih0, const float* __restrict__ Whh0,
    const float* __restrict__ bih0, const float* __restrict__ bhh0,
    const float* __restrict__ Wih1, const float* __restrict__ Whh1,
    const float* __restrict__ bih1, const float* __restrict__ bhh1,
    const float* __restrict__ Whead, const float* __restrict__ bhead,
    float* __restrict__ out)
{
    const int b  = blockIdx.x;
    const int tt = threadIdx.x;

    // ================= HEAD + LOSS =================
    if (b == 128) {
        if (tt >= 32) return;
        float w0[16], w1[16];
#pragma unroll
        for (int i = 0; i < 16; i++) {
            w0[i] = Whead[tt * 16 + i];
            w1[i] = Whead[HH + tt * 16 + i];
        }
        const float bb0 = bhead[0], bb1 = bhead[1];
        double acc = 0.0;
        const float* hrow = g_h2 + HH + tt * 16;    // +HH per step
        const int* cp = g_c2 + 2 * tt;              // this lane's 2 counters
        for (int t = 0; t < TT; t++, hrow += HH) {
            const int tgt = 8 * (t + 1);
            while (ld_acq(cp) < tgt || ld_acq(cp + 1) < tgt) {}
            float s0 = 0.f, s1 = 0.f;
#pragma unroll
            for (int q = 0; q < 4; q++) {
                float4 hv = __ldcg((const float4*)(hrow + 4 * q));
                s0 = fmaf(w0[4 * q + 0], hv.x, s0);
                s1 = fmaf(w1[4 * q + 0], hv.x, s1);
                s0 = fmaf(w0[4 * q + 1], hv.y, s0);
                s1 = fmaf(w1[4 * q + 1], hv.y, s1);
                s0 = fmaf(w0[4 * q + 2], hv.z, s0);
                s1 = fmaf(w1[4 * q + 2], hv.z, s1);
                s0 = fmaf(w0[4 * q + 3], hv.w, s0);
                s1 = fmaf(w1[4 * q + 3], hv.w, s1);
            }
#pragma unroll
            for (int m = 16; m >= 1; m >>= 1) {
                s0 += __shfl_xor_sync(0xffffffffu, s0, m);
                s1 += __shfl_xor_sync(0xffffffffu, s1, m);
            }
            if (tt == 0) {
                float z0 = s0 + bb0, z1 = s1 + bb1;
                float y0 = __ldg(truth + t * 2 + 0), y1 = __ldg(truth + t * 2 + 1);
                float t0 = y0 * fmaxf(logsigf_(z0), -100.0f)
                         + (1.0f - y0) * fmaxf(logsigf_(-z0), -100.0f);
                float t1 = y1 * fmaxf(logsigf_(z1), -100.0f)
                         + (1.0f - y1) * fmaxf(logsigf_(-z1), -100.0f);
                acc += (double)t0 + (double)t1;
            }
        }
        if (tt == 0) out[0] = (float)(-acc / (double)(TT * 2));
        return;
    }

    // ================= LSTM layer blocks =================
    const int role = b >> 6;            // 0 = layer 1, 1 = layer 2
    const int blk  = b & 63;
    const int j0   = blk * 8;
    const int p    = tt >> 3;           // row pair 0..31
    const int s    = tt & 7;            // 64-col slice
    const bool isB = (p >= 16);
    const int rr0  = 2 * (p & 15);
    const int gate = rr0 >> 3;
    const int jj   = rr0 & 7;

    const float* WM = isB ? (role ? Whh1 : Whh0) : (role ? Wih1 : Wih0);
    const size_t ro = (size_t)(gate * HH + j0 + jj) * HH;

    // register weights: 2 rows x 64-col slice, rotation-matched to LDS schedule
    ulonglong2 w0[16], w1[16];
#pragma unroll
    for (int i = 0; i < 16; i++) {
        int col = s * 64 + 4 * ((i + s) & 15);
        w0[i] = *(const ulonglong2*)(WM + ro + col);
        w1[i] = *(const ulonglong2*)(WM + ro + HH + col);
    }

    float bs0 = 0.f, bs1 = 0.f, bs2 = 0.f, bs3 = 0.f, c = 0.f;
    if (tt < 8) {
        const float* bi = role ? bih1 : bih0;
        const float* bh = role ? bhh1 : bhh0;
        bs0 = bi[0 * HH + j0 + tt] + bh[0 * HH + j0 + tt];
        bs1 = bi[1 * HH + j0 + tt] + bh[1 * HH + j0 + tt];
        bs2 = bi[2 * HH + j0 + tt] + bh[2 * HH + j0 + tt];
        bs3 = bi[3 * HH + j0 + tt] + bh[3 * HH + j0 + tt];
        c = c0[role * HH + j0 + tt];
    }

    __shared__ float vecs[2 * HH];   // [A(512) | B(512)]
    __shared__ float gsum[64];

    float* hOwn = role ? g_h2 : g_h1;
    int*   cOwn = role ? g_c2 : g_c1;

    // staging sources (advance by HH per step)
    const float4* px = (const float4*)x + tt;                  // layer-1 A
    const float* pA  = g_h1 + HH + 4 * tt;                     // layer-2 A: h1[t]
    const float* pB  = hOwn + 4 * (tt - 128);                  // B: own h[t-1]
    const int* cA = g_c1 + (tt >> 1);                          // counter for A float4
    const int* cB = cOwn + ((tt - 128) >> 1);                  // counter for B float4
    float* myOut = hOwn + HH + j0 + tt;                        // +HH per step (tt<8)

    for (int t = 0; t < TT; t++, px += 128, pA += HH, pB += HH, myOut += HH) {
        // ---- acquire-poll own counter, then load own float4 (same thread) ----
        if (tt < 128) {
            float4 va;
            if (role == 0) {
                va = __ldg(px);
            } else {
                const int tgt = 8 * (t + 1);
                while (ld_acq(cA) < tgt) {}
                va = __ldcg((const float4*)pA);
            }
            ((float4*)vecs)[tt] = va;
        } else {
            const int tgt = 8 * t;
            while (ld_acq(cB) < tgt) {}
            float4 vb = __ldcg((const float4*)pB);
            ((float4*)(vecs + HH))[tt - 128] = vb;
        }
        __syncthreads();

        // ---- dual-row packed matvec over this thread's 64-col slice ----
        const float* vb = vecs + (isB ? HH : 0) + s * 64;
        ull a0 = 0ull, a1 = 0ull;
#pragma unroll
        for (int i = 0; i < 16; i++) {
            int idx = 4 * ((i + s) & 15);
            ulonglong2 v = *(const ulonglong2*)(vb + idx);
            ffma2(a0, w0[i].x, v.x);
            ffma2(a0, w0[i].y, v.y);
            ffma2(a1, w1[i].x, v.x);
            ffma2(a1, w1[i].y, v.y);
        }
        float2 f0 = unpack2(a0), f1 = unpack2(a1);
        float s0 = f0.x + f0.y, s1 = f1.x + f1.y;
        s0 += __shfl_xor_sync(0xffffffffu, s0, 1);
        s1 += __shfl_xor_sync(0xffffffffu, s1, 1);
        s0 += __shfl_xor_sync(0xffffffffu, s0, 2);
        s1 += __shfl_xor_sync(0xffffffffu, s1, 2);
        s0 += __shfl_xor_sync(0xffffffffu, s0, 4);
        s1 += __shfl_xor_sync(0xffffffffu, s1, 4);
        if (s == 0) {
            int gr = (isB ? 32 : 0) + rr0;
            gsum[gr] = s0;
            gsum[gr + 1] = s1;
        }
        __syncthreads();

        // ---- gates + cell update + publish (STG then release-RED) ----
        if (tt < 8) {
            float p0 = gsum[0 * 8 + tt] + gsum[32 + 0 * 8 + tt] + bs0;
            float p1 = gsum[1 * 8 + tt] + gsum[32 + 1 * 8 + tt] + bs1;
            float p2 = gsum[2 * 8 + tt] + gsum[32 + 2 * 8 + tt] + bs2;
            float p3 = gsum[3 * 8 + tt] + gsum[32 + 3 * 8 + tt] + bs3;
            float ig = sig_fast(p0);
            float fg = sig_fast(p1);
            float gg = tanh_fast(p2);
            float og = sig_fast(p3);
            c = fg * c + ig * gg;
            float h = og * tanh_fast(c);
            *myOut = h;
            red_rel(cOwn + blk);
        }
        // hazard note: vecs/gsum reuse in iter t+1 is fenced by the two barriers
        // above (every thread must pass the t-iteration barriers first)
    }
}

extern "C" void kernel_launch(void* const* d_in, const int* in_sizes, int n_in,
                              void* d_out, int out_size) {
    const float* x     = (const float*)d_in[0];
    const float* truth = (const float*)d_in[1];
    const float* h0    = (const float*)d_in[2];
    const float* c0    = (const float*)d_in[3];
    const float* Wih0  = (const float*)d_in[4];
    const float* Whh0  = (const float*)d_in[5];
    const float* bih0  = (const float*)d_in[6];
    const float* bhh0  = (const float*)d_in[7];
    const float* Wih1  = (const float*)d_in[8];
    const float* Whh1  = (const float*)d_in[9];
    const float* bih1  = (const float*)d_in[10];
    const float* bhh1  = (const float*)d_in[11];
    const float* Whead = (const float*)d_in[12];
    const float* bhead = (const float*)d_in[13];
    float* out = (float*)d_out;

    clear_kernel<<<1, 512>>>(h0);
    lstm_kernel<<<129, 256>>>(x, truth, c0,
                              Wih0, Whh0, bih0, bhh0,
                              Wih1, Whh1, bih1, bhh1,
                              Whead, bhead, out);
}

// round 7
// speedup vs baseline: 1.3805x; 1.3805x over previous
#include <cuda_runtime.h>
#include <math.h>

typedef unsigned long long ull;
typedef unsigned int uint;

#define TT 8192
#define HH 512

// ---------------- scratch: packed {flag(hi32), h_bits(lo32)} mailboxes ----------------
// slot k holds h^(k); slot 0 = h0 with flag 0; slot t+1 written with flag t+1.
__device__ ull g_p1[(TT + 1) * HH];
__device__ ull g_p2[(TT + 1) * HH];

// ---------------- primitives ----------------
__device__ __forceinline__ ull ld_rlx(const ull* p) {
    ull v;
    asm volatile("ld.relaxed.gpu.global.u64 %0, [%1];" : "=l"(v) : "l"(p) : "memory");
    return v;
}
__device__ __forceinline__ void st_rlx(ull* p, ull v) {
    asm volatile("st.relaxed.gpu.global.u64 [%0], %1;" :: "l"(p), "l"(v) : "memory");
}
__device__ __forceinline__ ull packhf(unsigned flag, float h) {
    return ((ull)flag << 32) | (ull)__float_as_uint(h);
}
__device__ __forceinline__ float lo_f(ull v) { return __uint_as_float((unsigned)v); }
__device__ __forceinline__ unsigned hi_u(ull v) { return (unsigned)(v >> 32); }

__device__ __forceinline__ void ffma2(ull& acc, ull w, ull v) {
    asm("fma.rn.f32x2 %0, %1, %2, %0;" : "+l"(acc) : "l"(w), "l"(v));
}
__device__ __forceinline__ float2 unpack2(ull v) {
    float a, b;
    asm("mov.b64 {%0,%1}, %2;" : "=f"(a), "=f"(b) : "l"(v));
    return make_float2(a, b);
}
__device__ __forceinline__ float tanh_fast(float x) {
    float r;
    asm("tanh.approx.f32 %0, %1;" : "=f"(r) : "f"(x));
    return r;
}
__device__ __forceinline__ float sig_fast(float x) {
    return fmaf(tanh_fast(0.5f * x), 0.5f, 0.5f);
}
__device__ __forceinline__ float logsigf_(float z) {
    if (z >= 0.0f) return -log1pf(expf(-z));
    return z - log1pf(expf(z));
}

// ---------------- clear + seed ----------------
__global__ void clear_kernel(const float* __restrict__ h0) {
    size_t i = (size_t)blockIdx.x * blockDim.x + threadIdx.x;
    if (i < HH) {
        g_p1[i] = packhf(0u, h0[i]);
        g_p2[i] = packhf(0u, h0[HH + i]);
    }
    const size_t N2 = (size_t)TT * HH / 2;
    ulonglong2* a = (ulonglong2*)(g_p1 + HH);
    ulonglong2* b = (ulonglong2*)(g_p2 + HH);
    ulonglong2 z; z.x = 0ull; z.y = 0ull;
    size_t stride = (size_t)gridDim.x * blockDim.x;
    for (size_t k = i; k < N2; k += stride) { a[k] = z; b[k] = z; }
}

// ---------------- persistent pipelined LSTM ----------------
// 129 blocks x 256 threads.  (structure identical to the 10.76ms R3 kernel;
// only the poll loop is rewritten to re-load ONLY still-pending words)
//   blocks [0,64):   layer 1 (8 outputs each)
//   blocks [64,128): layer 2 (8 outputs each)
//   block 128:       head + BCE loss
__global__ void __launch_bounds__(256, 1) lstm_kernel(
    const float* __restrict__ x,
    const float* __restrict__ truth,
    const float* __restrict__ c0,
    const float* __restrict__ Wih0, const float* __restrict__ Whh0,
    const float* __restrict__ bih0, const float* __restrict__ bhh0,
    const float* __restrict__ Wih1, const float* __restrict__ Whh1,
    const float* __restrict__ bih1, const float* __restrict__ bhh1,
    const float* __restrict__ Whead, const float* __restrict__ bhead,
    float* __restrict__ out)
{
    const int b  = blockIdx.x;
    const int tt = threadIdx.x;

    // ================= HEAD + LOSS =================
    if (b == 128) {
        if (tt >= 32) return;
        float w0[16], w1[16];
#pragma unroll
        for (int i = 0; i < 16; i++) {
            w0[i] = Whead[tt * 16 + i];
            w1[i] = Whead[HH + tt * 16 + i];
        }
        const float bb0 = bhead[0], bb1 = bhead[1];
        double acc = 0.0;
        const ull* pe = g_p2 + HH + tt * 16;
        for (int t = 0; t < TT; t++, pe += HH) {
            const unsigned tgt = (unsigned)(t + 1);
            ull v[16];
            uint pend = 0xFFFFu;
            while (pend) {
                ull nv[16];
#pragma unroll
                for (int i = 0; i < 16; i++)
                    if (pend & (1u << i)) nv[i] = ld_rlx(pe + i);
#pragma unroll
                for (int i = 0; i < 16; i++)
                    if (pend & (1u << i)) {
                        if (hi_u(nv[i]) == tgt) { v[i] = nv[i]; pend &= ~(1u << i); }
                    }
            }
            float s0 = 0.f, s1 = 0.f;
#pragma unroll
            for (int i = 0; i < 16; i++) {
                float hv = lo_f(v[i]);
                s0 = fmaf(w0[i], hv, s0);
                s1 = fmaf(w1[i], hv, s1);
            }
#pragma unroll
            for (int m = 16; m >= 1; m >>= 1) {
                s0 += __shfl_xor_sync(0xffffffffu, s0, m);
                s1 += __shfl_xor_sync(0xffffffffu, s1, m);
            }
            if (tt == 0) {
                float z0 = s0 + bb0, z1 = s1 + bb1;
                float y0 = __ldg(truth + t * 2 + 0), y1 = __ldg(truth + t * 2 + 1);
                float t0 = y0 * fmaxf(logsigf_(z0), -100.0f)
                         + (1.0f - y0) * fmaxf(logsigf_(-z0), -100.0f);
                float t1 = y1 * fmaxf(logsigf_(z1), -100.0f)
                         + (1.0f - y1) * fmaxf(logsigf_(-z1), -100.0f);
                acc += (double)t0 + (double)t1;
            }
        }
        if (tt == 0) out[0] = (float)(-acc / (double)(TT * 2));
        return;
    }

    // ================= LSTM layer blocks =================
    const int role = b >> 6;
    const int j0   = (b & 63) * 8;
    const int p    = tt >> 3;           // row pair 0..31
    const int s    = tt & 7;            // 64-col slice
    const bool isB = (p >= 16);
    const int rr0  = 2 * (p & 15);
    const int gate = rr0 >> 3;
    const int jj   = rr0 & 7;

    const float* WM = isB ? (role ? Whh1 : Whh0) : (role ? Wih1 : Wih0);
    const size_t ro = (size_t)(gate * HH + j0 + jj) * HH;

    ulonglong2 w0[16], w1[16];
#pragma unroll
    for (int i = 0; i < 16; i++) {
        int col = s * 64 + 4 * ((i + s) & 15);
        w0[i] = *(const ulonglong2*)(WM + ro + col);
        w1[i] = *(const ulonglong2*)(WM + ro + HH + col);
    }

    float bs0 = 0.f, bs1 = 0.f, bs2 = 0.f, bs3 = 0.f, c = 0.f;
    if (tt < 8) {
        const float* bi = role ? bih1 : bih0;
        const float* bh = role ? bhh1 : bhh0;
        bs0 = bi[0 * HH + j0 + tt] + bh[0 * HH + j0 + tt];
        bs1 = bi[1 * HH + j0 + tt] + bh[1 * HH + j0 + tt];
        bs2 = bi[2 * HH + j0 + tt] + bh[2 * HH + j0 + tt];
        bs3 = bi[3 * HH + j0 + tt] + bh[3 * HH + j0 + tt];
        c = c0[role * HH + j0 + tt];
    }

    __shared__ float vecs[2 * HH];   // [A(512) | B(512)]
    __shared__ float gsum[64];

    ull* myP = role ? g_p2 : g_p1;
    const ull* pA = g_p1 + HH + 2 * tt;        // layer-2 A source: h1 slot t+1
    const ull* pB = myP + 2 * tt;              // own B source: h slot t
    const float2* px = (const float2*)x + tt;  // layer-1 A source
    ull* myOut = myP + HH + j0 + tt;           // producer store (tt<8)

    for (int t = 0; t < TT; t++, pA += HH, pB += HH, px += HH / 2, myOut += HH) {
        const unsigned tgtA = (unsigned)(t + 1);
        const unsigned tgtB = (unsigned)t;
        float2 va, vbv;

        // ---- pending-word poll: re-load ONLY words not yet flagged ----
        {
            ull a0, a1, b0, b1;
            uint pend = (role == 0) ? 0xCu : 0xFu;   // bits: 1=a0 2=a1 4=b0 8=b1
            if (role == 0) va = __ldg(px);
            do {
                ull n0, n1, n2, n3;
                if (pend & 1u) n0 = ld_rlx(pA);
                if (pend & 2u) n1 = ld_rlx(pA + 1);
                if (pend & 4u) n2 = ld_rlx(pB);
                if (pend & 8u) n3 = ld_rlx(pB + 1);
                if (pend & 1u) { if (hi_u(n0) == tgtA) { a0 = n0; pend &= ~1u; } }
                if (pend & 2u) { if (hi_u(n1) == tgtA) { a1 = n1; pend &= ~2u; } }
                if (pend & 4u) { if (hi_u(n2) == tgtB) { b0 = n2; pend &= ~4u; } }
                if (pend & 8u) { if (hi_u(n3) == tgtB) { b1 = n3; pend &= ~8u; } }
            } while (pend);
            if (role) va = make_float2(lo_f(a0), lo_f(a1));
            vbv = make_float2(lo_f(b0), lo_f(b1));
        }
        ((float2*)vecs)[tt] = va;
        ((float2*)(vecs + HH))[tt] = vbv;
        __syncthreads();

        // ---- dual-row packed matvec over this thread's 64-col slice ----
        const float* vb = vecs + (isB ? HH : 0) + s * 64;
        ull a0 = 0ull, a1 = 0ull;
#pragma unroll
        for (int i = 0; i < 16; i++) {
            int idx = 4 * ((i + s) & 15);
            ulonglong2 v = *(const ulonglong2*)(vb + idx);
            ffma2(a0, w0[i].x, v.x);
            ffma2(a0, w0[i].y, v.y);
            ffma2(a1, w1[i].x, v.x);
            ffma2(a1, w1[i].y, v.y);
        }
        float2 f0 = unpack2(a0), f1 = unpack2(a1);
        float s0 = f0.x + f0.y, s1 = f1.x + f1.y;
        s0 += __shfl_xor_sync(0xffffffffu, s0, 1);
        s1 += __shfl_xor_sync(0xffffffffu, s1, 1);
        s0 += __shfl_xor_sync(0xffffffffu, s0, 2);
        s1 += __shfl_xor_sync(0xffffffffu, s1, 2);
        s0 += __shfl_xor_sync(0xffffffffu, s0, 4);
        s1 += __shfl_xor_sync(0xffffffffu, s1, 4);
        if (s == 0) {
            int gr = (isB ? 32 : 0) + rr0;
            gsum[gr] = s0;
            gsum[gr + 1] = s1;
        }
        __syncthreads();

        // ---- gates + cell update + fused publish ----
        if (tt < 8) {
            float p0 = gsum[0 * 8 + tt] + gsum[32 + 0 * 8 + tt] + bs0;
            float p1 = gsum[1 * 8 + tt] + gsum[32 + 1 * 8 + tt] + bs1;
            float p2 = gsum[2 * 8 + tt] + gsum[32 + 2 * 8 + tt] + bs2;
            float p3 = gsum[3 * 8 + tt] + gsum[32 + 3 * 8 + tt] + bs3;
            float ig = sig_fast(p0);
            float fg = sig_fast(p1);
            float gg = tanh_fast(p2);
            float og = sig_fast(p3);
            c = fg * c + ig * gg;
            float h = og * tanh_fast(c);
            st_rlx(myOut, packhf((unsigned)(t + 1), h));
        }
    }
}

extern "C" void kernel_launch(void* const* d_in, const int* in_sizes, int n_in,
                              void* d_out, int out_size) {
    const float* x     = (const float*)d_in[0];
    const float* truth = (const float*)d_in[1];
    const float* h0    = (const float*)d_in[2];
    const float* c0    = (const float*)d_in[3];
    const float* Wih0  = (const float*)d_in[4];
    const float* Whh0  = (const float*)d_in[5];
    const float* bih0  = (const float*)d_in[6];
    const float* bhh0  = (const float*)d_in[7];
    const float* Wih1  = (const float*)d_in[8];
    const float* Whh1  = (const float*)d_in[9];
    const float* bih1  = (const float*)d_in[10];
    const float* bhh1  = (const float*)d_in[11];
    const float* Whead = (const float*)d_in[12];
    const float* bhead = (const float*)d_in[13];
    float* out = (float*)d_out;

    clear_kernel<<<256, 1024>>>(h0);
    lstm_kernel<<<129, 256>>>(x, truth, c0,
                              Wih0, Whh0, bih0, bhh0,
                              Wih1, Whh1, bih1, bhh1,
                              Whead, bhead, out);
}